// round 11
// baseline (speedup 1.0000x reference)
#include <cuda_runtime.h>
#include <cuda_fp16.h>
#include <math.h>
#include <stdint.h>

// Problem constants
#define BB 4
#define TT 8192
#define CC 128
#define RRC 64       // residual channels
#define SSC 256      // skip channels
#define LLC 16

// Output region offsets (pytree flatten order: out, in_acts, cond)
#define OUT_SZ     (BB*256*TT)
#define INACT_OFF  (OUT_SZ)
#define INACT_SZ   (BB*LLC*128*TT)
#define COND_OFF   (INACT_OFF + INACT_SZ)

#define SQRT_HALF 0.70710678118654752440f

// Scratch (device globals; no allocation allowed)
__device__ float g_x0[BB*RRC*TT];
__device__ float g_x1[BB*RRC*TT];

// Gated activations, fp16 hi/lo planes, layout [l][b][t][64ch]
__device__ __align__(16) __half g_act_h[LLC*BB*TT*64];
__device__ __align__(16) __half g_act_l[LLC*BB*TT*64];

// Pre-packed A-operand fragments (fp16 hi/lo), mma.m16n8k16 layout.
__device__ uint4 g_wd_h[LLC*2048];
__device__ uint4 g_wd_l[LLC*2048];
__device__ uint4 g_ws_h[LLC*2048];
__device__ uint4 g_ws_l[LLC*2048];
__device__ uint4 g_wr_h[15*512];
__device__ uint4 g_wr_l[15*512];
__device__ uint4 g_wc_h[LLC*2048];  // cond_W frags (hi/lo)
__device__ uint4 g_wc_l[LLC*2048];
__device__ uint4 g_wo_h[8192];      // conv_out_W frags (hi only)
__device__ uint4 g_we_h[8192];      // conv_end_W frags (hi only)

// ===========================================================================
// helpers
// ===========================================================================
__device__ __forceinline__ uint32_t smem_u32(const void* p) {
    uint32_t a;
    asm("{ .reg .u64 t; cvta.to.shared.u64 t, %1; cvt.u32.u64 %0, t; }" : "=r"(a) : "l"(p));
    return a;
}
__device__ __forceinline__ void ldsm4(uint32_t* r, uint32_t a) {
    asm volatile("ldmatrix.sync.aligned.m8n8.x4.shared.b16 {%0,%1,%2,%3}, [%4];"
        : "=r"(r[0]), "=r"(r[1]), "=r"(r[2]), "=r"(r[3]) : "r"(a));
}
__device__ __forceinline__ void mma16816(float* d, const uint32_t* a, const uint32_t* b) {
    asm volatile(
        "mma.sync.aligned.m16n8k16.row.col.f32.f16.f16.f32 "
        "{%0,%1,%2,%3}, {%4,%5,%6,%7}, {%8,%9}, {%0,%1,%2,%3};"
        : "+f"(d[0]), "+f"(d[1]), "+f"(d[2]), "+f"(d[3])
        : "r"(a[0]), "r"(a[1]), "r"(a[2]), "r"(a[3]), "r"(b[0]), "r"(b[1]));
}
__device__ __forceinline__ void ldB(uint32_t* fr, const char* sb, int off, int stride,
                                    int n0, int k0, int lane) {
    uint32_t a = smem_u32(sb + off) +
        (uint32_t)(((n0 + ((lane >> 4) & 1) * 8 + (lane & 7)) * stride
                    + k0 + ((lane >> 3) & 1) * 8) << 1);
    ldsm4(fr, a);
}
__device__ __forceinline__ void split2(float v, __half& h, __half& l) {
    h = __float2half_rn(v);
    l = __float2half_rn(v - __half2float(h));
}
__device__ __forceinline__ uint32_t packh2(__half a, __half b) {
    __half2 h = __halves2half2(a, b);
    return *(uint32_t*)&h;
}

#define CP_ASYNC16(dst, src) \
    asm volatile("cp.async.ca.shared.global [%0], [%1], 16;" :: "r"(dst), "l"(src))
#define CP_COMMIT() asm volatile("cp.async.commit_group;" ::: "memory")
#define CP_WAIT0()  asm volatile("cp.async.wait_group 0;" ::: "memory")

// ===========================================================================
// merged weight pre-pack kernel
// ===========================================================================
__device__ __forceinline__ void pack8(const float* v, uint4& hi, uint4& lo) {
    __half eh[8], el[8];
    #pragma unroll
    for (int i = 0; i < 8; i++) split2(v[i], eh[i], el[i]);
    hi.x = packh2(eh[0], eh[1]); hi.y = packh2(eh[2], eh[3]);
    hi.z = packh2(eh[4], eh[5]); hi.w = packh2(eh[6], eh[7]);
    lo.x = packh2(el[0], el[1]); lo.y = packh2(el[2], el[3]);
    lo.z = packh2(el[4], el[5]); lo.w = packh2(el[6], el[7]);
}

__global__ void pack_all_kernel(const float* __restrict__ dilate_W,
                                const float* __restrict__ cond_W,
                                const float* __restrict__ skip_W,
                                const float* __restrict__ res_W,
                                const float* __restrict__ Wout,
                                const float* __restrict__ Wend,
                                uint4* __restrict__ wdh, uint4* __restrict__ wdl,
                                uint4* __restrict__ wch, uint4* __restrict__ wcl,
                                uint4* __restrict__ wsh, uint4* __restrict__ wsl,
                                uint4* __restrict__ wrh, uint4* __restrict__ wrl,
                                uint4* __restrict__ woh, uint4* __restrict__ weh)
{
    const int bx = blockIdx.x, tid = threadIdx.x;
    static const int dr[8] = {0,0,8,8,0,0,8,8};
    static const int dc[8] = {0,1,0,1,8,9,8,9};

    if (bx < 128) {                       // dilate
        int idx = bx*256 + tid;
        int lane = idx & 31, fi = idx >> 5;
        int ks = fi & 7, mt = (fi >> 3) & 7, l = fi >> 6;
        int r = mt*16 + (lane >> 2), cb = ks*16 + (lane & 3)*2;
        float v[8];
        #pragma unroll
        for (int i = 0; i < 8; i++) {
            int row = r + dr[i], col = cb + dc[i];
            v[i] = (col < 64)
                ? dilate_W[((l*128 + row)*64 + col)*2 + 0]
                : dilate_W[((l*128 + row)*64 + (col - 64))*2 + 1];
        }
        uint4 hi, lo; pack8(v, hi, lo);
        wdh[idx] = hi; wdl[idx] = lo;
    } else if (bx < 256) {                // cond
        int idx = (bx-128)*256 + tid;
        int lane = idx & 31, fi = idx >> 5;
        int ks = fi & 7, mt = (fi >> 3) & 7, l = fi >> 6;
        int r = mt*16 + (lane >> 2), cb = ks*16 + (lane & 3)*2;
        float v[8];
        #pragma unroll
        for (int i = 0; i < 8; i++)
            v[i] = cond_W[((size_t)(l*128 + r + dr[i]))*CC + cb + dc[i]];
        uint4 hi, lo; pack8(v, hi, lo);
        wch[idx] = hi; wcl[idx] = lo;
    } else if (bx < 384) {                // skip
        int idx = (bx-256)*256 + tid;
        int lane = idx & 31, fi = idx >> 5;
        int ks = fi & 3, mt = (fi >> 2) & 15, l = fi >> 6;
        int r = mt*16 + (lane >> 2), cb = ks*16 + (lane & 3)*2;
        float v[8];
        #pragma unroll
        for (int i = 0; i < 8; i++)
            v[i] = skip_W[((size_t)l*256 + r + dr[i])*64 + cb + dc[i]];
        uint4 hi, lo; pack8(v, hi, lo);
        wsh[idx] = hi; wsl[idx] = lo;
    } else if (bx < 414) {                // res
        int idx = (bx-384)*256 + tid;
        if (idx >= 7680) return;
        int lane = idx & 31, fi = idx >> 5;
        int ks = fi & 3, mt = (fi >> 2) & 3, l = fi >> 4;
        int r = mt*16 + (lane >> 2), cb = ks*16 + (lane & 3)*2;
        float v[8];
        #pragma unroll
        for (int i = 0; i < 8; i++)
            v[i] = res_W[((size_t)l*64 + r + dr[i])*64 + cb + dc[i]];
        uint4 hi, lo; pack8(v, hi, lo);
        wrh[idx] = hi; wrl[idx] = lo;
    } else {                              // Wout / Wend (hi only)
        const float* W = (bx < 446) ? Wout : Wend;
        uint4* outp    = (bx < 446) ? woh : weh;
        int idx = ((bx < 446) ? (bx-414) : (bx-446))*256 + tid;
        int lane = idx & 31, fi = idx >> 5;
        int ks = fi & 15, mt = fi >> 4;
        int r = mt*16 + (lane >> 2), cb = ks*16 + (lane & 3)*2;
        __half eh[8];
        #pragma unroll
        for (int i = 0; i < 8; i++)
            eh[i] = __float2half_rn(W[(r + dr[i])*256 + cb + dc[i]]);
        uint4 hi;
        hi.x = packh2(eh[0], eh[1]); hi.y = packh2(eh[2], eh[3]);
        hi.z = packh2(eh[4], eh[5]); hi.w = packh2(eh[6], eh[7]);
        outp[idx] = hi;
    }
}

// ===========================================================================
// embed
// ===========================================================================
__global__ void embed_kernel(const int* __restrict__ tokens,
                             const float* __restrict__ embed,
                             float* __restrict__ x0)
{
    __shared__ int tok[256];
    const int t0 = blockIdx.x * 256;
    const int b  = blockIdx.y;
    tok[threadIdx.x] = tokens[b*TT + t0 + threadIdx.x];
    __syncthreads();
    const int v = tok[threadIdx.x];
    #pragma unroll 4
    for (int r = 0; r < RRC; r++)
        x0[(b*RRC + r)*TT + t0 + threadIdx.x] = embed[v*RRC + r];
}

// ===========================================================================
// cond v3: stage features tile ONCE, loop over all 16 layers.
// 128 threads, t-tile 32, grid (T/32=256, B). smem 17408 -> 6 CTAs/SM.
// ===========================================================================
#define C3_FH 0
#define C3_FL 8704
#define C3_SMEM 17408

__global__ void __launch_bounds__(128, 6)
cond_mma3_kernel(const float* __restrict__ features,
                 const uint4* __restrict__ wc_h, const uint4* __restrict__ wc_l,
                 const float* __restrict__ cond_b,
                 float* __restrict__ cond_out)
{
    extern __shared__ char sb[];
    const int tid = threadIdx.x, wid = tid >> 5, lane = tid & 31;
    const int g = lane >> 2, tg = lane & 3;
    const int t0 = blockIdx.x * 32;
    const int b  = blockIdx.y;

    // stage features tile [t:32][k:128] hi/lo once
    {
        __half* FH = (__half*)(sb + C3_FH);
        __half* FL = (__half*)(sb + C3_FL);
        for (int e = tid; e < 4096; e += 128) {
            int t = e & 31, k = e >> 5;
            float v = features[((size_t)b*CC + k)*TT + t0 + t];
            __half h, lo; split2(v, h, lo);
            FH[t*136 + k] = h; FL[t*136 + k] = lo;
        }
    }
    __syncthreads();

    const int m0 = wid * 32;

    for (int l = 0; l < LLC; l++) {
        float acc[2][4][4] = {};
        const uint4* ph = wc_h + (size_t)l * 2048;
        const uint4* pl = wc_l + (size_t)l * 2048;
        #pragma unroll
        for (int ks = 0; ks < 8; ks++) {
            uint4 A0h = ph[((wid*2    )*8 + ks)*32 + lane];
            uint4 A1h = ph[((wid*2 + 1)*8 + ks)*32 + lane];
            uint4 A0l = pl[((wid*2    )*8 + ks)*32 + lane];
            uint4 A1l = pl[((wid*2 + 1)*8 + ks)*32 + lane];
            #pragma unroll
            for (int p = 0; p < 2; p++) {
                uint32_t bh[4], bl[4];
                ldB(bh, sb, C3_FH, 136, p*16, ks*16, lane);
                ldB(bl, sb, C3_FL, 136, p*16, ks*16, lane);
                #pragma unroll
                for (int q = 0; q < 2; q++) {
                    int nt = p*2 + q;
                    mma16816(acc[0][nt], (const uint32_t*)&A0h, &bh[q*2]);
                    mma16816(acc[0][nt], (const uint32_t*)&A0h, &bl[q*2]);
                    mma16816(acc[0][nt], (const uint32_t*)&A0l, &bh[q*2]);
                    mma16816(acc[1][nt], (const uint32_t*)&A1h, &bh[q*2]);
                    mma16816(acc[1][nt], (const uint32_t*)&A1h, &bl[q*2]);
                    mma16816(acc[1][nt], (const uint32_t*)&A1l, &bh[q*2]);
                }
            }
        }
        #pragma unroll
        for (int mt = 0; mt < 2; mt++)
            #pragma unroll
            for (int r = 0; r < 2; r++) {
                int o = m0 + mt*16 + r*8 + g;
                float bias = cond_b[l*128 + o];
                float* row = cond_out + ((size_t)(b*LLC + l)*128 + o)*TT + t0;
                #pragma unroll
                for (int nt = 0; nt < 4; nt++) {
                    int tc = nt*8 + 2*tg;
                    float2 rv = make_float2(acc[mt][nt][r*2+0] + bias,
                                            acc[mt][nt][r*2+1] + bias);
                    *(float2*)(row + tc) = rv;
                }
            }
    }
}

// ===========================================================================
// layer v6: t-tile 32, 128 threads, 6 CTAs/SM; cond prefetched via cp.async
// under GEMM1. grid (T/32=256, B).
// smem phase1: XH[32][136] @0 (8704), XL @8704; CND fp32[128][36] @17408 (18432)
// smem phase2: ABUF fp32[128][34] @0 (17408); AH[32][72] @17408, AL @22016
//              (AH/AL alias dead CND). total 35840 -> 6x35840 = 215KB <= 228KB.
// ===========================================================================
#define L6_XH   0
#define L6_XL   8704
#define L6_CND  17408
#define L6_ABUF 0
#define L6_AH   17408
#define L6_AL   22016
#define L6_SMEM 35840

__global__ void __launch_bounds__(128, 6)
layer_mma6_kernel(const float* __restrict__ x_in,
                  float* __restrict__ x_out,
                  const uint4* __restrict__ wd_h, const uint4* __restrict__ wd_l,
                  const float* __restrict__ dilate_b,
                  const uint4* __restrict__ wr_h, const uint4* __restrict__ wr_l,
                  const float* __restrict__ res_b,
                  const float* __restrict__ cond_g,
                  float* __restrict__ inacts_g,
                  __half* __restrict__ act_h, __half* __restrict__ act_l,
                  int layer, int dil, int last)
{
    extern __shared__ char sb[];
    uint32_t sb_u = smem_u32(sb);
    const int tid = threadIdx.x, wid = tid >> 5, lane = tid & 31;
    const int g = lane >> 2, tg = lane & 3;
    const int t0 = blockIdx.x * 32;
    const int b  = blockIdx.y;

    // ---- phase1: cp.async cond tile [128o][32t]; stage X halves
    {
        const float* cbase = cond_g + ((size_t)(b*LLC + layer)*128)*TT + t0;
        for (int i = tid; i < 1024; i += 128) {
            int o = i >> 3, j = i & 7;
            CP_ASYNC16(sb_u + L6_CND + o*144 + j*16, cbase + (size_t)o*TT + j*4);
        }
        CP_COMMIT();

        __half* XH = (__half*)(sb + L6_XH);
        __half* XL = (__half*)(sb + L6_XL);
        const float* xb = x_in + (size_t)b * RRC * TT;
        for (int e = tid; e < 4096; e += 128) {
            int t = e & 31, ks = e >> 5;
            float v;
            if (ks < 64) {
                int tp = t0 + t - dil;
                v = (tp >= 0) ? xb[ks*TT + tp] : 0.f;
            } else {
                v = xb[(ks - 64)*TT + t0 + t];
            }
            __half h, lo; split2(v, h, lo);
            XH[t*136 + ks] = h; XL[t*136 + ks] = lo;
        }
    }
    __syncthreads();

    // ---- GEMM1: ia[128 o][32 t] = Wd @ Xcat (K=128), 3-pass
    const int m0 = wid * 32;
    float acc[2][4][4] = {};
    {
        const uint4* ph = wd_h + (size_t)layer * 2048;
        const uint4* pl = wd_l + (size_t)layer * 2048;
        #pragma unroll
        for (int ks = 0; ks < 8; ks++) {
            uint4 A0h = ph[((wid*2    )*8 + ks)*32 + lane];
            uint4 A1h = ph[((wid*2 + 1)*8 + ks)*32 + lane];
            uint4 A0l = pl[((wid*2    )*8 + ks)*32 + lane];
            uint4 A1l = pl[((wid*2 + 1)*8 + ks)*32 + lane];
            #pragma unroll
            for (int p = 0; p < 2; p++) {
                uint32_t bh[4], bl[4];
                ldB(bh, sb, L6_XH, 136, p*16, ks*16, lane);
                ldB(bl, sb, L6_XL, 136, p*16, ks*16, lane);
                #pragma unroll
                for (int q = 0; q < 2; q++) {
                    int nt = p*2 + q;
                    mma16816(acc[0][nt], (const uint32_t*)&A0h, &bh[q*2]);
                    mma16816(acc[0][nt], (const uint32_t*)&A0h, &bl[q*2]);
                    mma16816(acc[0][nt], (const uint32_t*)&A0l, &bh[q*2]);
                    mma16816(acc[1][nt], (const uint32_t*)&A1h, &bh[q*2]);
                    mma16816(acc[1][nt], (const uint32_t*)&A1h, &bl[q*2]);
                    mma16816(acc[1][nt], (const uint32_t*)&A1l, &bh[q*2]);
                }
            }
        }
    }
    CP_WAIT0();
    __syncthreads();   // X reads done (ABUF aliases X); CND landed

    // ---- epilogue1: ia -> gmem in_acts; a = ia + cond(smem) -> ABUF
    {
        float* abuf = (float*)(sb + L6_ABUF);
        const float* CND = (const float*)(sb + L6_CND);
        #pragma unroll
        for (int mt = 0; mt < 2; mt++)
            #pragma unroll
            for (int r = 0; r < 2; r++) {
                int o = m0 + mt*16 + r*8 + g;
                float bias = dilate_b[layer*128 + o];
                float* iap = inacts_g + ((size_t)(b*LLC + layer)*128 + o)*TT + t0;
                const float* cp = CND + o*36;
                float* ab = abuf + o*34;
                #pragma unroll
                for (int nt = 0; nt < 4; nt++) {
                    int tc = nt*8 + 2*tg;
                    float2 cv = *(const float2*)(cp + tc);
                    float ia0 = acc[mt][nt][r*2+0] + bias;
                    float ia1 = acc[mt][nt][r*2+1] + bias;
                    *(float2*)(iap + tc) = make_float2(ia0, ia1);
                    *(float2*)(ab + tc) = make_float2(ia0 + cv.x, ia1 + cv.y);
                }
            }
    }
    __syncthreads();

    // ---- gated activation -> AH/AL (aliases dead CND)
    {
        float* abuf = (float*)(sb + L6_ABUF);
        __half* AH = (__half*)(sb + L6_AH);
        __half* AL = (__half*)(sb + L6_AL);
        for (int e = tid; e < 2048; e += 128) {
            int t = e & 31, kk = e >> 5;
            float a0 = abuf[kk*34 + t];
            float a1 = abuf[(kk + 64)*34 + t];
            float act = tanhf(a0) * (1.f / (1.f + __expf(-a1)));
            __half h, lo; split2(act, h, lo);
            AH[t*72 + kk] = h; AL[t*72 + kk] = lo;
        }
    }
    __syncthreads();

    // ---- store act planes (consumed by skiphead)
    {
        uint4* gh = (uint4*)(act_h + ((size_t)(layer*BB + b)*TT + t0)*64);
        uint4* gl = (uint4*)(act_l + ((size_t)(layer*BB + b)*TT + t0)*64);
        for (int i = tid; i < 256; i += 128) {
            int t = i >> 3, j = i & 7;
            gh[t*8 + j] = *(const uint4*)(sb + L6_AH + t*144 + j*16);
            gl[t*8 + j] = *(const uint4*)(sb + L6_AL + t*144 + j*16);
        }
    }

    // ---- GEMM3: res (M=64, N=32, K=64), 3-pass; residual x update
    if (!last) {
        const int mi3 = wid >> 1, ni3 = wid & 1;
        const int m0r = mi3 * 32, n0r = ni3 * 16;
        const uint4* ph = wr_h + (size_t)layer * 512;
        const uint4* pl = wr_l + (size_t)layer * 512;
        float acc3[2][2][4] = {};
        #pragma unroll
        for (int ks = 0; ks < 4; ks++) {
            uint4 A0h = ph[((mi3*2    )*4 + ks)*32 + lane];
            uint4 A1h = ph[((mi3*2 + 1)*4 + ks)*32 + lane];
            uint4 A0l = pl[((mi3*2    )*4 + ks)*32 + lane];
            uint4 A1l = pl[((mi3*2 + 1)*4 + ks)*32 + lane];
            uint32_t bh[4], bl[4];
            ldB(bh, sb, L6_AH, 72, n0r, ks*16, lane);
            ldB(bl, sb, L6_AL, 72, n0r, ks*16, lane);
            #pragma unroll
            for (int q = 0; q < 2; q++) {
                mma16816(acc3[0][q], (const uint32_t*)&A0h, &bh[q*2]);
                mma16816(acc3[0][q], (const uint32_t*)&A0h, &bl[q*2]);
                mma16816(acc3[0][q], (const uint32_t*)&A0l, &bh[q*2]);
                mma16816(acc3[1][q], (const uint32_t*)&A1h, &bh[q*2]);
                mma16816(acc3[1][q], (const uint32_t*)&A1h, &bl[q*2]);
                mma16816(acc3[1][q], (const uint32_t*)&A1l, &bh[q*2]);
            }
        }
        #pragma unroll
        for (int mt = 0; mt < 2; mt++)
            #pragma unroll
            for (int r = 0; r < 2; r++) {
                int o = m0r + mt*16 + r*8 + g;
                float rb = res_b[layer*RRC + o];
                const float* xi = x_in  + ((size_t)b*RRC + o)*TT + t0;
                float*       xo = x_out + ((size_t)b*RRC + o)*TT + t0;
                #pragma unroll
                for (int nt = 0; nt < 2; nt++) {
                    int tc = n0r + nt*8 + 2*tg;
                    float2 xv = *(const float2*)(xi + tc);
                    float2 rv;
                    rv.x = (acc3[mt][nt][r*2+0] + rb + xv.x) * SQRT_HALF;
                    rv.y = (acc3[mt][nt][r*2+1] + rb + xv.y) * SQRT_HALF;
                    *(float2*)(xo + tc) = rv;
                }
            }
    }
}

// ===========================================================================
// skiphead v2 (unchanged)
// ===========================================================================
#define TB_SZ  18432
#define T2_SMEM 36864

__global__ void __launch_bounds__(256, 2)
skiphead2_kernel(const __half* __restrict__ act_h, const __half* __restrict__ act_l,
                 const uint4* __restrict__ ws_h, const uint4* __restrict__ ws_l,
                 const float* __restrict__ skip_b,
                 const uint4* __restrict__ wo_h, const uint4* __restrict__ we_h,
                 float* __restrict__ out)
{
    extern __shared__ char sb[];
    uint32_t sb_u = smem_u32(sb);
    const int tid = threadIdx.x, wid = tid >> 5, lane = tid & 31;
    const int g = lane >> 2, tg = lane & 3;
    const int t0 = blockIdx.x * 64;
    const int b  = blockIdx.y;

    float acc[2][8][4] = {};

    auto stage = [&](int l, int buf) {
        const uint4* gh = (const uint4*)(act_h + ((size_t)(l*BB + b)*TT + t0)*64);
        const uint4* gl = (const uint4*)(act_l + ((size_t)(l*BB + b)*TT + t0)*64);
        uint32_t dh = sb_u + buf*TB_SZ;
        uint32_t dl = dh + 9216;
        for (int i = tid; i < 512; i += 256) {
            int t = i >> 3, j = i & 7;
            CP_ASYNC16(dh + t*144 + j*16, gh + t*8 + j);
            CP_ASYNC16(dl + t*144 + j*16, gl + t*8 + j);
        }
        CP_COMMIT();
    };

    stage(0, 0);
    CP_WAIT0();
    __syncthreads();

    for (int l = 0; l < LLC; l++) {
        int cur = l & 1;
        if (l + 1 < LLC) stage(l + 1, cur ^ 1);

        int offH = cur*TB_SZ, offL = offH + 9216;
        const uint4* ph = ws_h + (size_t)l * 2048;
        const uint4* pl = ws_l + (size_t)l * 2048;
        for (int ks = 0; ks < 4; ks++) {
            uint4 A0h = ph[((wid*2    )*4 + ks)*32 + lane];
            uint4 A1h = ph[((wid*2 + 1)*4 + ks)*32 + lane];
            uint4 A0l = pl[((wid*2    )*4 + ks)*32 + lane];
            uint4 A1l = pl[((wid*2 + 1)*4 + ks)*32 + lane];
            #pragma unroll
            for (int p = 0; p < 4; p++) {
                uint32_t bh[4], bl[4];
                ldB(bh, sb, offH, 72, p*16, ks*16, lane);
                ldB(bl, sb, offL, 72, p*16, ks*16, lane);
                #pragma unroll
                for (int q = 0; q < 2; q++) {
                    int nt = p*2 + q;
                    mma16816(acc[0][nt], (const uint32_t*)&A0h, &bh[q*2]);
                    mma16816(acc[0][nt], (const uint32_t*)&A0h, &bl[q*2]);
                    mma16816(acc[0][nt], (const uint32_t*)&A0l, &bh[q*2]);
                    mma16816(acc[1][nt], (const uint32_t*)&A1h, &bh[q*2]);
                    mma16816(acc[1][nt], (const uint32_t*)&A1h, &bl[q*2]);
                    mma16816(acc[1][nt], (const uint32_t*)&A1l, &bh[q*2]);
                }
            }
        }
        if (l + 1 < LLC) CP_WAIT0();
        __syncthreads();
    }

    {
        __half* H = (__half*)sb;
        #pragma unroll
        for (int mt = 0; mt < 2; mt++)
            #pragma unroll
            for (int r = 0; r < 2; r++) {
                int o = wid*32 + mt*16 + r*8 + g;
                float bs = 0.f;
                #pragma unroll
                for (int l = 0; l < LLC; l++) bs += skip_b[l*SSC + o];
                #pragma unroll
                for (int nt = 0; nt < 8; nt++) {
                    int t = nt*8 + tg*2;
                    H[t*264 + o]     = __float2half_rn(fmaxf(acc[mt][nt][r*2+0] + bs, 0.f));
                    H[(t+1)*264 + o] = __float2half_rn(fmaxf(acc[mt][nt][r*2+1] + bs, 0.f));
                }
            }
    }
    __syncthreads();

    float acc2[2][8][4] = {};
    for (int ks = 0; ks < 16; ks++) {
        uint4 A0 = wo_h[((wid*2    )*16 + ks)*32 + lane];
        uint4 A1 = wo_h[((wid*2 + 1)*16 + ks)*32 + lane];
        #pragma unroll
        for (int p = 0; p < 4; p++) {
            uint32_t bh[4];
            ldB(bh, sb, 0, 264, p*16, ks*16, lane);
            #pragma unroll
            for (int q = 0; q < 2; q++) {
                int nt = p*2 + q;
                mma16816(acc2[0][nt], (const uint32_t*)&A0, &bh[q*2]);
                mma16816(acc2[1][nt], (const uint32_t*)&A1, &bh[q*2]);
            }
        }
    }
    __syncthreads();
    {
        __half* H = (__half*)sb;
        #pragma unroll
        for (int mt = 0; mt < 2; mt++)
            #pragma unroll
            for (int r = 0; r < 2; r++) {
                int o = wid*32 + mt*16 + r*8 + g;
                #pragma unroll
                for (int nt = 0; nt < 8; nt++) {
                    int t = nt*8 + tg*2;
                    H[t*264 + o]     = __float2half_rn(fmaxf(acc2[mt][nt][r*2+0], 0.f));
                    H[(t+1)*264 + o] = __float2half_rn(fmaxf(acc2[mt][nt][r*2+1], 0.f));
                }
            }
    }
    __syncthreads();

    float acc3[2][8][4] = {};
    for (int ks = 0; ks < 16; ks++) {
        uint4 A0 = we_h[((wid*2    )*16 + ks)*32 + lane];
        uint4 A1 = we_h[((wid*2 + 1)*16 + ks)*32 + lane];
        #pragma unroll
        for (int p = 0; p < 4; p++) {
            uint32_t bh[4];
            ldB(bh, sb, 0, 264, p*16, ks*16, lane);
            #pragma unroll
            for (int q = 0; q < 2; q++) {
                int nt = p*2 + q;
                mma16816(acc3[0][nt], (const uint32_t*)&A0, &bh[q*2]);
                mma16816(acc3[1][nt], (const uint32_t*)&A1, &bh[q*2]);
            }
        }
    }
    #pragma unroll
    for (int mt = 0; mt < 2; mt++)
        #pragma unroll
        for (int r = 0; r < 2; r++) {
            int o = wid*32 + mt*16 + r*8 + g;
            float* op = out + ((size_t)b*256 + o)*TT;
            #pragma unroll
            for (int nt = 0; nt < 8; nt++) {
                int tc = t0 + nt*8 + 2*tg;
                if (tc + 1 < TT) op[tc + 1] = acc3[mt][nt][r*2+0];
                if (tc + 2 < TT) op[tc + 2] = acc3[mt][nt][r*2+1];
            }
        }
    if (blockIdx.x == 0) out[((size_t)b*256 + tid)*TT] = 0.f;
}

// ===========================================================================
extern "C" void kernel_launch(void* const* d_in, const int* in_sizes, int n_in,
                              void* d_out, int out_size)
{
    const float* features   = (const float*)d_in[0];
    const int*   tokens     = (const int*)  d_in[1];
    const float* embed      = (const float*)d_in[2];
    const float* cond_W     = (const float*)d_in[3];
    const float* cond_b     = (const float*)d_in[4];
    const float* dilate_W   = (const float*)d_in[5];
    const float* dilate_b   = (const float*)d_in[6];
    const float* res_W      = (const float*)d_in[7];
    const float* res_b      = (const float*)d_in[8];
    const float* skip_W     = (const float*)d_in[9];
    const float* skip_b     = (const float*)d_in[10];
    const float* conv_out_W = (const float*)d_in[11];
    const float* conv_end_W = (const float*)d_in[12];
    float* outp = (float*)d_out;

    float* out_r   = outp;
    float* inact_r = outp + INACT_OFF;
    float* cond_r  = outp + COND_OFF;

    float *x0, *x1;
    __half *ah, *al;
    uint4 *wdh, *wdl, *wsh, *wsl, *wrh, *wrl, *wch, *wcl, *woh, *weh;
    cudaGetSymbolAddress((void**)&x0,  g_x0);
    cudaGetSymbolAddress((void**)&x1,  g_x1);
    cudaGetSymbolAddress((void**)&ah,  g_act_h);
    cudaGetSymbolAddress((void**)&al,  g_act_l);
    cudaGetSymbolAddress((void**)&wdh, g_wd_h);
    cudaGetSymbolAddress((void**)&wdl, g_wd_l);
    cudaGetSymbolAddress((void**)&wsh, g_ws_h);
    cudaGetSymbolAddress((void**)&wsl, g_ws_l);
    cudaGetSymbolAddress((void**)&wrh, g_wr_h);
    cudaGetSymbolAddress((void**)&wrl, g_wr_l);
    cudaGetSymbolAddress((void**)&wch, g_wc_h);
    cudaGetSymbolAddress((void**)&wcl, g_wc_l);
    cudaGetSymbolAddress((void**)&woh, g_wo_h);
    cudaGetSymbolAddress((void**)&weh, g_we_h);

    static const int DIL[LLC] = {1,2,4,8,16,32,64,128,256,1,2,4,8,16,32,64};

    cudaFuncSetAttribute(cond_mma3_kernel,  cudaFuncAttributeMaxDynamicSharedMemorySize, C3_SMEM);
    cudaFuncSetAttribute(layer_mma6_kernel, cudaFuncAttributeMaxDynamicSharedMemorySize, L6_SMEM);
    cudaFuncSetAttribute(skiphead2_kernel,  cudaFuncAttributeMaxDynamicSharedMemorySize, T2_SMEM);

    pack_all_kernel<<<478, 256>>>(dilate_W, cond_W, skip_W, res_W, conv_out_W, conv_end_W,
                                  wdh, wdl, wch, wcl, wsh, wsl, wrh, wrl, woh, weh);

    embed_kernel<<<dim3(TT/256, BB), 256>>>(tokens, embed, x0);
    cond_mma3_kernel<<<dim3(TT/32, BB), 128, C3_SMEM>>>(features, wch, wcl, cond_b, cond_r);

    float* xi = x0;
    float* xo = x1;
    for (int i = 0; i < LLC; i++) {
        layer_mma6_kernel<<<dim3(TT/32, BB), 128, L6_SMEM>>>(
            xi, xo, wdh, wdl, dilate_b, wrh, wrl, res_b,
            cond_r, inact_r, ah, al,
            i, DIL[i], (i == LLC-1) ? 1 : 0);
        float* t = xi; xi = xo; xo = t;
    }

    skiphead2_kernel<<<dim3(TT/64, BB), 256, T2_SMEM>>>(
        ah, al, wsh, wsl, skip_b, woh, weh, out_r);
}

// round 12
// speedup vs baseline: 1.1889x; 1.1889x over previous
#include <cuda_runtime.h>
#include <cuda_fp16.h>
#include <math.h>
#include <stdint.h>

// Problem constants
#define BB 4
#define TT 8192
#define CC 128
#define RRC 64       // residual channels
#define SSC 256      // skip channels
#define LLC 16

// Output region offsets (pytree flatten order: out, in_acts, cond)
#define OUT_SZ     (BB*256*TT)
#define INACT_OFF  (OUT_SZ)
#define INACT_SZ   (BB*LLC*128*TT)
#define COND_OFF   (INACT_OFF + INACT_SZ)

#define SQRT_HALF 0.70710678118654752440f

// Scratch (device globals; no allocation allowed)
__device__ float g_x0[BB*RRC*TT];
__device__ float g_x1[BB*RRC*TT];

// Gated activations, fp16 hi/lo planes, layout [l][b][t][64ch]
__device__ __align__(16) __half g_act_h[LLC*BB*TT*64];
__device__ __align__(16) __half g_act_l[LLC*BB*TT*64];

// Pre-packed A-operand fragments (fp16 hi/lo), mma.m16n8k16 layout.
__device__ uint4 g_wd_h[LLC*2048];
__device__ uint4 g_wd_l[LLC*2048];
__device__ uint4 g_ws_h[LLC*2048];
__device__ uint4 g_ws_l[LLC*2048];
__device__ uint4 g_wr_h[15*512];
__device__ uint4 g_wr_l[15*512];
__device__ uint4 g_wc_h[LLC*2048];  // cond_W frags (hi/lo)
__device__ uint4 g_wc_l[LLC*2048];
__device__ uint4 g_wo_h[8192];      // conv_out_W frags (hi only)
__device__ uint4 g_we_h[8192];      // conv_end_W frags (hi only)

// ===========================================================================
// helpers
// ===========================================================================
__device__ __forceinline__ uint32_t smem_u32(const void* p) {
    uint32_t a;
    asm("{ .reg .u64 t; cvta.to.shared.u64 t, %1; cvt.u32.u64 %0, t; }" : "=r"(a) : "l"(p));
    return a;
}
__device__ __forceinline__ void ldsm4(uint32_t* r, uint32_t a) {
    asm volatile("ldmatrix.sync.aligned.m8n8.x4.shared.b16 {%0,%1,%2,%3}, [%4];"
        : "=r"(r[0]), "=r"(r[1]), "=r"(r[2]), "=r"(r[3]) : "r"(a));
}
__device__ __forceinline__ void mma16816(float* d, const uint32_t* a, const uint32_t* b) {
    asm volatile(
        "mma.sync.aligned.m16n8k16.row.col.f32.f16.f16.f32 "
        "{%0,%1,%2,%3}, {%4,%5,%6,%7}, {%8,%9}, {%0,%1,%2,%3};"
        : "+f"(d[0]), "+f"(d[1]), "+f"(d[2]), "+f"(d[3])
        : "r"(a[0]), "r"(a[1]), "r"(a[2]), "r"(a[3]), "r"(b[0]), "r"(b[1]));
}
__device__ __forceinline__ void ldB(uint32_t* fr, const char* sb, int off, int stride,
                                    int n0, int k0, int lane) {
    uint32_t a = smem_u32(sb + off) +
        (uint32_t)(((n0 + ((lane >> 4) & 1) * 8 + (lane & 7)) * stride
                    + k0 + ((lane >> 3) & 1) * 8) << 1);
    ldsm4(fr, a);
}
__device__ __forceinline__ void split2(float v, __half& h, __half& l) {
    h = __float2half_rn(v);
    l = __float2half_rn(v - __half2float(h));
}
__device__ __forceinline__ uint32_t packh2(__half a, __half b) {
    __half2 h = __halves2half2(a, b);
    return *(uint32_t*)&h;
}

#define CP_ASYNC16(dst, src) \
    asm volatile("cp.async.ca.shared.global [%0], [%1], 16;" :: "r"(dst), "l"(src))
#define CP_COMMIT() asm volatile("cp.async.commit_group;" ::: "memory")
#define CP_WAIT0()  asm volatile("cp.async.wait_group 0;" ::: "memory")

// ===========================================================================
// merged weight pre-pack kernel
// ===========================================================================
__device__ __forceinline__ void pack8(const float* v, uint4& hi, uint4& lo) {
    __half eh[8], el[8];
    #pragma unroll
    for (int i = 0; i < 8; i++) split2(v[i], eh[i], el[i]);
    hi.x = packh2(eh[0], eh[1]); hi.y = packh2(eh[2], eh[3]);
    hi.z = packh2(eh[4], eh[5]); hi.w = packh2(eh[6], eh[7]);
    lo.x = packh2(el[0], el[1]); lo.y = packh2(el[2], el[3]);
    lo.z = packh2(el[4], el[5]); lo.w = packh2(el[6], el[7]);
}

__global__ void pack_all_kernel(const float* __restrict__ dilate_W,
                                const float* __restrict__ cond_W,
                                const float* __restrict__ skip_W,
                                const float* __restrict__ res_W,
                                const float* __restrict__ Wout,
                                const float* __restrict__ Wend,
                                uint4* __restrict__ wdh, uint4* __restrict__ wdl,
                                uint4* __restrict__ wch, uint4* __restrict__ wcl,
                                uint4* __restrict__ wsh, uint4* __restrict__ wsl,
                                uint4* __restrict__ wrh, uint4* __restrict__ wrl,
                                uint4* __restrict__ woh, uint4* __restrict__ weh)
{
    const int bx = blockIdx.x, tid = threadIdx.x;
    static const int dr[8] = {0,0,8,8,0,0,8,8};
    static const int dc[8] = {0,1,0,1,8,9,8,9};

    if (bx < 128) {                       // dilate
        int idx = bx*256 + tid;
        int lane = idx & 31, fi = idx >> 5;
        int ks = fi & 7, mt = (fi >> 3) & 7, l = fi >> 6;
        int r = mt*16 + (lane >> 2), cb = ks*16 + (lane & 3)*2;
        float v[8];
        #pragma unroll
        for (int i = 0; i < 8; i++) {
            int row = r + dr[i], col = cb + dc[i];
            v[i] = (col < 64)
                ? dilate_W[((l*128 + row)*64 + col)*2 + 0]
                : dilate_W[((l*128 + row)*64 + (col - 64))*2 + 1];
        }
        uint4 hi, lo; pack8(v, hi, lo);
        wdh[idx] = hi; wdl[idx] = lo;
    } else if (bx < 256) {                // cond
        int idx = (bx-128)*256 + tid;
        int lane = idx & 31, fi = idx >> 5;
        int ks = fi & 7, mt = (fi >> 3) & 7, l = fi >> 6;
        int r = mt*16 + (lane >> 2), cb = ks*16 + (lane & 3)*2;
        float v[8];
        #pragma unroll
        for (int i = 0; i < 8; i++)
            v[i] = cond_W[((size_t)(l*128 + r + dr[i]))*CC + cb + dc[i]];
        uint4 hi, lo; pack8(v, hi, lo);
        wch[idx] = hi; wcl[idx] = lo;
    } else if (bx < 384) {                // skip
        int idx = (bx-256)*256 + tid;
        int lane = idx & 31, fi = idx >> 5;
        int ks = fi & 3, mt = (fi >> 2) & 15, l = fi >> 6;
        int r = mt*16 + (lane >> 2), cb = ks*16 + (lane & 3)*2;
        float v[8];
        #pragma unroll
        for (int i = 0; i < 8; i++)
            v[i] = skip_W[((size_t)l*256 + r + dr[i])*64 + cb + dc[i]];
        uint4 hi, lo; pack8(v, hi, lo);
        wsh[idx] = hi; wsl[idx] = lo;
    } else if (bx < 414) {                // res
        int idx = (bx-384)*256 + tid;
        if (idx >= 7680) return;
        int lane = idx & 31, fi = idx >> 5;
        int ks = fi & 3, mt = (fi >> 2) & 3, l = fi >> 4;
        int r = mt*16 + (lane >> 2), cb = ks*16 + (lane & 3)*2;
        float v[8];
        #pragma unroll
        for (int i = 0; i < 8; i++)
            v[i] = res_W[((size_t)l*64 + r + dr[i])*64 + cb + dc[i]];
        uint4 hi, lo; pack8(v, hi, lo);
        wrh[idx] = hi; wrl[idx] = lo;
    } else {                              // Wout / Wend (hi only)
        const float* W = (bx < 446) ? Wout : Wend;
        uint4* outp    = (bx < 446) ? woh : weh;
        int idx = ((bx < 446) ? (bx-414) : (bx-446))*256 + tid;
        int lane = idx & 31, fi = idx >> 5;
        int ks = fi & 15, mt = fi >> 4;
        int r = mt*16 + (lane >> 2), cb = ks*16 + (lane & 3)*2;
        __half eh[8];
        #pragma unroll
        for (int i = 0; i < 8; i++)
            eh[i] = __float2half_rn(W[(r + dr[i])*256 + cb + dc[i]]);
        uint4 hi;
        hi.x = packh2(eh[0], eh[1]); hi.y = packh2(eh[2], eh[3]);
        hi.z = packh2(eh[4], eh[5]); hi.w = packh2(eh[6], eh[7]);
        outp[idx] = hi;
    }
}

// ===========================================================================
// embed
// ===========================================================================
__global__ void embed_kernel(const int* __restrict__ tokens,
                             const float* __restrict__ embed,
                             float* __restrict__ x0)
{
    __shared__ int tok[256];
    const int t0 = blockIdx.x * 256;
    const int b  = blockIdx.y;
    tok[threadIdx.x] = tokens[b*TT + t0 + threadIdx.x];
    __syncthreads();
    const int v = tok[threadIdx.x];
    #pragma unroll 4
    for (int r = 0; r < RRC; r++)
        x0[(b*RRC + r)*TT + t0 + threadIdx.x] = embed[v*RRC + r];
}

// ===========================================================================
// cond v4: features staged once, loop over 16 layers; reg-lean 3-pass,
// 128 threads, 8 CTAs/SM. grid (T/32=256, B). smem 17408.
// ===========================================================================
#define C4_FH 0
#define C4_FL 8704
#define C4_SMEM 17408

__global__ void __launch_bounds__(128, 8)
cond_mma4_kernel(const float* __restrict__ features,
                 const uint4* __restrict__ wc_h, const uint4* __restrict__ wc_l,
                 const float* __restrict__ cond_b,
                 float* __restrict__ cond_out)
{
    extern __shared__ char sb[];
    const int tid = threadIdx.x, wid = tid >> 5, lane = tid & 31;
    const int g = lane >> 2, tg = lane & 3;
    const int t0 = blockIdx.x * 32;
    const int b  = blockIdx.y;

    {
        __half* FH = (__half*)(sb + C4_FH);
        __half* FL = (__half*)(sb + C4_FL);
        for (int e = tid; e < 4096; e += 128) {
            int t = e & 31, k = e >> 5;
            float v = features[((size_t)b*CC + k)*TT + t0 + t];
            __half h, lo; split2(v, h, lo);
            FH[t*136 + k] = h; FL[t*136 + k] = lo;
        }
    }
    __syncthreads();

    const int m0 = wid * 32;

    for (int l = 0; l < LLC; l++) {
        float acc[2][4][4] = {};
        const uint4* ph = wc_h + (size_t)l * 2048;
        const uint4* pl = wc_l + (size_t)l * 2048;
        #pragma unroll
        for (int ks = 0; ks < 8; ks++) {
            #pragma unroll
            for (int p = 0; p < 2; p++) {
                uint32_t bh[4], bl[4];
                ldB(bh, sb, C4_FH, 136, p*16, ks*16, lane);
                ldB(bl, sb, C4_FL, 136, p*16, ks*16, lane);
                {
                    uint4 A0 = ph[((wid*2    )*8 + ks)*32 + lane];
                    uint4 A1 = ph[((wid*2 + 1)*8 + ks)*32 + lane];
                    #pragma unroll
                    for (int q = 0; q < 2; q++) {
                        int nt = p*2 + q;
                        mma16816(acc[0][nt], (const uint32_t*)&A0, &bh[q*2]);
                        mma16816(acc[0][nt], (const uint32_t*)&A0, &bl[q*2]);
                        mma16816(acc[1][nt], (const uint32_t*)&A1, &bh[q*2]);
                        mma16816(acc[1][nt], (const uint32_t*)&A1, &bl[q*2]);
                    }
                }
                {
                    uint4 A0 = pl[((wid*2    )*8 + ks)*32 + lane];
                    uint4 A1 = pl[((wid*2 + 1)*8 + ks)*32 + lane];
                    #pragma unroll
                    for (int q = 0; q < 2; q++) {
                        int nt = p*2 + q;
                        mma16816(acc[0][nt], (const uint32_t*)&A0, &bh[q*2]);
                        mma16816(acc[1][nt], (const uint32_t*)&A1, &bh[q*2]);
                    }
                }
            }
        }
        #pragma unroll
        for (int mt = 0; mt < 2; mt++)
            #pragma unroll
            for (int r = 0; r < 2; r++) {
                int o = m0 + mt*16 + r*8 + g;
                float bias = cond_b[l*128 + o];
                float* row = cond_out + ((size_t)(b*LLC + l)*128 + o)*TT + t0;
                #pragma unroll
                for (int nt = 0; nt < 4; nt++) {
                    int tc = nt*8 + 2*tg;
                    float2 rv = make_float2(acc[mt][nt][r*2+0] + bias,
                                            acc[mt][nt][r*2+1] + bias);
                    *(float2*)(row + tc) = rv;
                }
            }
    }
}

// ===========================================================================
// layer v7: v5 semantics (cond read from gmem in epilogue), reg-lean 3-pass
// loops, 128 threads, 8 CTAs/SM -> grid 1024 = single wave.
// smem: phase1 XH[32][136] @0 (8704), XL @8704 -> 17408
//       phase2 ABUF fp32[128][34] @0 (17408), AH[32][72] @17408, AL @22016
// total 26624; 8x26624 = 213KB <= 228KB.
// ===========================================================================
#define L7_XH   0
#define L7_XL   8704
#define L7_ABUF 0
#define L7_AH   17408
#define L7_AL   22016
#define L7_SMEM 26624

__global__ void __launch_bounds__(128, 8)
layer_mma7_kernel(const float* __restrict__ x_in,
                  float* __restrict__ x_out,
                  const uint4* __restrict__ wd_h, const uint4* __restrict__ wd_l,
                  const float* __restrict__ dilate_b,
                  const uint4* __restrict__ wr_h, const uint4* __restrict__ wr_l,
                  const float* __restrict__ res_b,
                  const float* __restrict__ cond_g,
                  float* __restrict__ inacts_g,
                  __half* __restrict__ act_h, __half* __restrict__ act_l,
                  int layer, int dil, int last)
{
    extern __shared__ char sb[];
    const int tid = threadIdx.x, wid = tid >> 5, lane = tid & 31;
    const int g = lane >> 2, tg = lane & 3;
    const int t0 = blockIdx.x * 32;
    const int b  = blockIdx.y;

    // ---- stage X halves: [t:32][ks:128]
    {
        __half* XH = (__half*)(sb + L7_XH);
        __half* XL = (__half*)(sb + L7_XL);
        const float* xb = x_in + (size_t)b * RRC * TT;
        for (int e = tid; e < 4096; e += 128) {
            int t = e & 31, ks = e >> 5;
            float v;
            if (ks < 64) {
                int tp = t0 + t - dil;
                v = (tp >= 0) ? xb[ks*TT + tp] : 0.f;
            } else {
                v = xb[(ks - 64)*TT + t0 + t];
            }
            __half h, lo; split2(v, h, lo);
            XH[t*136 + ks] = h; XL[t*136 + ks] = lo;
        }
    }
    __syncthreads();

    // ---- GEMM1: ia[128 o][32 t] = Wd @ Xcat (K=128), reg-lean 3-pass
    const int m0 = wid * 32;
    float acc[2][4][4] = {};
    {
        const uint4* ph = wd_h + (size_t)layer * 2048;
        const uint4* pl = wd_l + (size_t)layer * 2048;
        #pragma unroll
        for (int ks = 0; ks < 8; ks++) {
            #pragma unroll
            for (int p = 0; p < 2; p++) {
                uint32_t bh[4], bl[4];
                ldB(bh, sb, L7_XH, 136, p*16, ks*16, lane);
                ldB(bl, sb, L7_XL, 136, p*16, ks*16, lane);
                {
                    uint4 A0 = ph[((wid*2    )*8 + ks)*32 + lane];
                    uint4 A1 = ph[((wid*2 + 1)*8 + ks)*32 + lane];
                    #pragma unroll
                    for (int q = 0; q < 2; q++) {
                        int nt = p*2 + q;
                        mma16816(acc[0][nt], (const uint32_t*)&A0, &bh[q*2]);
                        mma16816(acc[0][nt], (const uint32_t*)&A0, &bl[q*2]);
                        mma16816(acc[1][nt], (const uint32_t*)&A1, &bh[q*2]);
                        mma16816(acc[1][nt], (const uint32_t*)&A1, &bl[q*2]);
                    }
                }
                {
                    uint4 A0 = pl[((wid*2    )*8 + ks)*32 + lane];
                    uint4 A1 = pl[((wid*2 + 1)*8 + ks)*32 + lane];
                    #pragma unroll
                    for (int q = 0; q < 2; q++) {
                        int nt = p*2 + q;
                        mma16816(acc[0][nt], (const uint32_t*)&A0, &bh[q*2]);
                        mma16816(acc[1][nt], (const uint32_t*)&A1, &bh[q*2]);
                    }
                }
            }
        }
    }
    __syncthreads();   // X reads done before ABUF aliases X

    // ---- epilogue1: ia -> gmem in_acts; a = ia + cond(gmem) -> ABUF
    {
        float* abuf = (float*)(sb + L7_ABUF);
        #pragma unroll
        for (int mt = 0; mt < 2; mt++)
            #pragma unroll
            for (int r = 0; r < 2; r++) {
                int o = m0 + mt*16 + r*8 + g;
                float bias = dilate_b[layer*128 + o];
                size_t rowoff = ((size_t)(b*LLC + layer)*128 + o)*TT + t0;
                float*       iap = inacts_g + rowoff;
                const float* cp  = cond_g + rowoff;
                float* ab = abuf + o*34;
                #pragma unroll
                for (int nt = 0; nt < 4; nt++) {
                    int tc = nt*8 + 2*tg;
                    float2 cv = *(const float2*)(cp + tc);
                    float ia0 = acc[mt][nt][r*2+0] + bias;
                    float ia1 = acc[mt][nt][r*2+1] + bias;
                    *(float2*)(iap + tc) = make_float2(ia0, ia1);
                    *(float2*)(ab + tc) = make_float2(ia0 + cv.x, ia1 + cv.y);
                }
            }
    }
    __syncthreads();

    // ---- gated activation -> AH/AL
    {
        float* abuf = (float*)(sb + L7_ABUF);
        __half* AH = (__half*)(sb + L7_AH);
        __half* AL = (__half*)(sb + L7_AL);
        for (int e = tid; e < 2048; e += 128) {
            int t = e & 31, kk = e >> 5;
            float a0 = abuf[kk*34 + t];
            float a1 = abuf[(kk + 64)*34 + t];
            float act = tanhf(a0) * (1.f / (1.f + __expf(-a1)));
            __half h, lo; split2(act, h, lo);
            AH[t*72 + kk] = h; AL[t*72 + kk] = lo;
        }
    }
    __syncthreads();

    // ---- store act planes (consumed by skiphead)
    {
        uint4* gh = (uint4*)(act_h + ((size_t)(layer*BB + b)*TT + t0)*64);
        uint4* gl = (uint4*)(act_l + ((size_t)(layer*BB + b)*TT + t0)*64);
        for (int i = tid; i < 256; i += 128) {
            int t = i >> 3, j = i & 7;
            gh[t*8 + j] = *(const uint4*)(sb + L7_AH + t*144 + j*16);
            gl[t*8 + j] = *(const uint4*)(sb + L7_AL + t*144 + j*16);
        }
    }

    // ---- GEMM3: res (M=64, N=32, K=64), reg-lean 3-pass; residual x update
    if (!last) {
        const int mi3 = wid >> 1, ni3 = wid & 1;
        const int m0r = mi3 * 32, n0r = ni3 * 16;
        const uint4* ph = wr_h + (size_t)layer * 512;
        const uint4* pl = wr_l + (size_t)layer * 512;
        float acc3[2][2][4] = {};
        #pragma unroll
        for (int ks = 0; ks < 4; ks++) {
            uint32_t bh[4], bl[4];
            ldB(bh, sb, L7_AH, 72, n0r, ks*16, lane);
            ldB(bl, sb, L7_AL, 72, n0r, ks*16, lane);
            {
                uint4 A0 = ph[((mi3*2    )*4 + ks)*32 + lane];
                uint4 A1 = ph[((mi3*2 + 1)*4 + ks)*32 + lane];
                #pragma unroll
                for (int q = 0; q < 2; q++) {
                    mma16816(acc3[0][q], (const uint32_t*)&A0, &bh[q*2]);
                    mma16816(acc3[0][q], (const uint32_t*)&A0, &bl[q*2]);
                    mma16816(acc3[1][q], (const uint32_t*)&A1, &bh[q*2]);
                    mma16816(acc3[1][q], (const uint32_t*)&A1, &bl[q*2]);
                }
            }
            {
                uint4 A0 = pl[((mi3*2    )*4 + ks)*32 + lane];
                uint4 A1 = pl[((mi3*2 + 1)*4 + ks)*32 + lane];
                #pragma unroll
                for (int q = 0; q < 2; q++) {
                    mma16816(acc3[0][q], (const uint32_t*)&A0, &bh[q*2]);
                    mma16816(acc3[1][q], (const uint32_t*)&A1, &bh[q*2]);
                }
            }
        }
        #pragma unroll
        for (int mt = 0; mt < 2; mt++)
            #pragma unroll
            for (int r = 0; r < 2; r++) {
                int o = m0r + mt*16 + r*8 + g;
                float rb = res_b[layer*RRC + o];
                const float* xi = x_in  + ((size_t)b*RRC + o)*TT + t0;
                float*       xo = x_out + ((size_t)b*RRC + o)*TT + t0;
                #pragma unroll
                for (int nt = 0; nt < 2; nt++) {
                    int tc = n0r + nt*8 + 2*tg;
                    float2 xv = *(const float2*)(xi + tc);
                    float2 rv;
                    rv.x = (acc3[mt][nt][r*2+0] + rb + xv.x) * SQRT_HALF;
                    rv.y = (acc3[mt][nt][r*2+1] + rb + xv.y) * SQRT_HALF;
                    *(float2*)(xo + tc) = rv;
                }
            }
    }
}

// ===========================================================================
// skiphead v2 (unchanged)
// ===========================================================================
#define TB_SZ  18432
#define T2_SMEM 36864

__global__ void __launch_bounds__(256, 2)
skiphead2_kernel(const __half* __restrict__ act_h, const __half* __restrict__ act_l,
                 const uint4* __restrict__ ws_h, const uint4* __restrict__ ws_l,
                 const float* __restrict__ skip_b,
                 const uint4* __restrict__ wo_h, const uint4* __restrict__ we_h,
                 float* __restrict__ out)
{
    extern __shared__ char sb[];
    uint32_t sb_u = smem_u32(sb);
    const int tid = threadIdx.x, wid = tid >> 5, lane = tid & 31;
    const int g = lane >> 2, tg = lane & 3;
    const int t0 = blockIdx.x * 64;
    const int b  = blockIdx.y;

    float acc[2][8][4] = {};

    auto stage = [&](int l, int buf) {
        const uint4* gh = (const uint4*)(act_h + ((size_t)(l*BB + b)*TT + t0)*64);
        const uint4* gl = (const uint4*)(act_l + ((size_t)(l*BB + b)*TT + t0)*64);
        uint32_t dh = sb_u + buf*TB_SZ;
        uint32_t dl = dh + 9216;
        for (int i = tid; i < 512; i += 256) {
            int t = i >> 3, j = i & 7;
            CP_ASYNC16(dh + t*144 + j*16, gh + t*8 + j);
            CP_ASYNC16(dl + t*144 + j*16, gl + t*8 + j);
        }
        CP_COMMIT();
    };

    stage(0, 0);
    CP_WAIT0();
    __syncthreads();

    for (int l = 0; l < LLC; l++) {
        int cur = l & 1;
        if (l + 1 < LLC) stage(l + 1, cur ^ 1);

        int offH = cur*TB_SZ, offL = offH + 9216;
        const uint4* ph = ws_h + (size_t)l * 2048;
        const uint4* pl = ws_l + (size_t)l * 2048;
        for (int ks = 0; ks < 4; ks++) {
            uint4 A0h = ph[((wid*2    )*4 + ks)*32 + lane];
            uint4 A1h = ph[((wid*2 + 1)*4 + ks)*32 + lane];
            uint4 A0l = pl[((wid*2    )*4 + ks)*32 + lane];
            uint4 A1l = pl[((wid*2 + 1)*4 + ks)*32 + lane];
            #pragma unroll
            for (int p = 0; p < 4; p++) {
                uint32_t bh[4], bl[4];
                ldB(bh, sb, offH, 72, p*16, ks*16, lane);
                ldB(bl, sb, offL, 72, p*16, ks*16, lane);
                #pragma unroll
                for (int q = 0; q < 2; q++) {
                    int nt = p*2 + q;
                    mma16816(acc[0][nt], (const uint32_t*)&A0h, &bh[q*2]);
                    mma16816(acc[0][nt], (const uint32_t*)&A0h, &bl[q*2]);
                    mma16816(acc[0][nt], (const uint32_t*)&A0l, &bh[q*2]);
                    mma16816(acc[1][nt], (const uint32_t*)&A1h, &bh[q*2]);
                    mma16816(acc[1][nt], (const uint32_t*)&A1h, &bl[q*2]);
                    mma16816(acc[1][nt], (const uint32_t*)&A1l, &bh[q*2]);
                }
            }
        }
        if (l + 1 < LLC) CP_WAIT0();
        __syncthreads();
    }

    {
        __half* H = (__half*)sb;
        #pragma unroll
        for (int mt = 0; mt < 2; mt++)
            #pragma unroll
            for (int r = 0; r < 2; r++) {
                int o = wid*32 + mt*16 + r*8 + g;
                float bs = 0.f;
                #pragma unroll
                for (int l = 0; l < LLC; l++) bs += skip_b[l*SSC + o];
                #pragma unroll
                for (int nt = 0; nt < 8; nt++) {
                    int t = nt*8 + tg*2;
                    H[t*264 + o]     = __float2half_rn(fmaxf(acc[mt][nt][r*2+0] + bs, 0.f));
                    H[(t+1)*264 + o] = __float2half_rn(fmaxf(acc[mt][nt][r*2+1] + bs, 0.f));
                }
            }
    }
    __syncthreads();

    float acc2[2][8][4] = {};
    for (int ks = 0; ks < 16; ks++) {
        uint4 A0 = wo_h[((wid*2    )*16 + ks)*32 + lane];
        uint4 A1 = wo_h[((wid*2 + 1)*16 + ks)*32 + lane];
        #pragma unroll
        for (int p = 0; p < 4; p++) {
            uint32_t bh[4];
            ldB(bh, sb, 0, 264, p*16, ks*16, lane);
            #pragma unroll
            for (int q = 0; q < 2; q++) {
                int nt = p*2 + q;
                mma16816(acc2[0][nt], (const uint32_t*)&A0, &bh[q*2]);
                mma16816(acc2[1][nt], (const uint32_t*)&A1, &bh[q*2]);
            }
        }
    }
    __syncthreads();
    {
        __half* H = (__half*)sb;
        #pragma unroll
        for (int mt = 0; mt < 2; mt++)
            #pragma unroll
            for (int r = 0; r < 2; r++) {
                int o = wid*32 + mt*16 + r*8 + g;
                #pragma unroll
                for (int nt = 0; nt < 8; nt++) {
                    int t = nt*8 + tg*2;
                    H[t*264 + o]     = __float2half_rn(fmaxf(acc2[mt][nt][r*2+0], 0.f));
                    H[(t+1)*264 + o] = __float2half_rn(fmaxf(acc2[mt][nt][r*2+1], 0.f));
                }
            }
    }
    __syncthreads();

    float acc3[2][8][4] = {};
    for (int ks = 0; ks < 16; ks++) {
        uint4 A0 = we_h[((wid*2    )*16 + ks)*32 + lane];
        uint4 A1 = we_h[((wid*2 + 1)*16 + ks)*32 + lane];
        #pragma unroll
        for (int p = 0; p < 4; p++) {
            uint32_t bh[4];
            ldB(bh, sb, 0, 264, p*16, ks*16, lane);
            #pragma unroll
            for (int q = 0; q < 2; q++) {
                int nt = p*2 + q;
                mma16816(acc3[0][nt], (const uint32_t*)&A0, &bh[q*2]);
                mma16816(acc3[1][nt], (const uint32_t*)&A1, &bh[q*2]);
            }
        }
    }
    #pragma unroll
    for (int mt = 0; mt < 2; mt++)
        #pragma unroll
        for (int r = 0; r < 2; r++) {
            int o = wid*32 + mt*16 + r*8 + g;
            float* op = out + ((size_t)b*256 + o)*TT;
            #pragma unroll
            for (int nt = 0; nt < 8; nt++) {
                int tc = t0 + nt*8 + 2*tg;
                if (tc + 1 < TT) op[tc + 1] = acc3[mt][nt][r*2+0];
                if (tc + 2 < TT) op[tc + 2] = acc3[mt][nt][r*2+1];
            }
        }
    if (blockIdx.x == 0) out[((size_t)b*256 + tid)*TT] = 0.f;
}

// ===========================================================================
extern "C" void kernel_launch(void* const* d_in, const int* in_sizes, int n_in,
                              void* d_out, int out_size)
{
    const float* features   = (const float*)d_in[0];
    const int*   tokens     = (const int*)  d_in[1];
    const float* embed      = (const float*)d_in[2];
    const float* cond_W     = (const float*)d_in[3];
    const float* cond_b     = (const float*)d_in[4];
    const float* dilate_W   = (const float*)d_in[5];
    const float* dilate_b   = (const float*)d_in[6];
    const float* res_W      = (const float*)d_in[7];
    const float* res_b      = (const float*)d_in[8];
    const float* skip_W     = (const float*)d_in[9];
    const float* skip_b     = (const float*)d_in[10];
    const float* conv_out_W = (const float*)d_in[11];
    const float* conv_end_W = (const float*)d_in[12];
    float* outp = (float*)d_out;

    float* out_r   = outp;
    float* inact_r = outp + INACT_OFF;
    float* cond_r  = outp + COND_OFF;

    float *x0, *x1;
    __half *ah, *al;
    uint4 *wdh, *wdl, *wsh, *wsl, *wrh, *wrl, *wch, *wcl, *woh, *weh;
    cudaGetSymbolAddress((void**)&x0,  g_x0);
    cudaGetSymbolAddress((void**)&x1,  g_x1);
    cudaGetSymbolAddress((void**)&ah,  g_act_h);
    cudaGetSymbolAddress((void**)&al,  g_act_l);
    cudaGetSymbolAddress((void**)&wdh, g_wd_h);
    cudaGetSymbolAddress((void**)&wdl, g_wd_l);
    cudaGetSymbolAddress((void**)&wsh, g_ws_h);
    cudaGetSymbolAddress((void**)&wsl, g_ws_l);
    cudaGetSymbolAddress((void**)&wrh, g_wr_h);
    cudaGetSymbolAddress((void**)&wrl, g_wr_l);
    cudaGetSymbolAddress((void**)&wch, g_wc_h);
    cudaGetSymbolAddress((void**)&wcl, g_wc_l);
    cudaGetSymbolAddress((void**)&woh, g_wo_h);
    cudaGetSymbolAddress((void**)&weh, g_we_h);

    static const int DIL[LLC] = {1,2,4,8,16,32,64,128,256,1,2,4,8,16,32,64};

    cudaFuncSetAttribute(cond_mma4_kernel,  cudaFuncAttributeMaxDynamicSharedMemorySize, C4_SMEM);
    cudaFuncSetAttribute(layer_mma7_kernel, cudaFuncAttributeMaxDynamicSharedMemorySize, L7_SMEM);
    cudaFuncSetAttribute(skiphead2_kernel,  cudaFuncAttributeMaxDynamicSharedMemorySize, T2_SMEM);

    pack_all_kernel<<<478, 256>>>(dilate_W, cond_W, skip_W, res_W, conv_out_W, conv_end_W,
                                  wdh, wdl, wch, wcl, wsh, wsl, wrh, wrl, woh, weh);

    embed_kernel<<<dim3(TT/256, BB), 256>>>(tokens, embed, x0);
    cond_mma4_kernel<<<dim3(TT/32, BB), 128, C4_SMEM>>>(features, wch, wcl, cond_b, cond_r);

    float* xi = x0;
    float* xo = x1;
    for (int i = 0; i < LLC; i++) {
        layer_mma7_kernel<<<dim3(TT/32, BB), 128, L7_SMEM>>>(
            xi, xo, wdh, wdl, dilate_b, wrh, wrl, res_b,
            cond_r, inact_r, ah, al,
            i, DIL[i], (i == LLC-1) ? 1 : 0);
        float* t = xi; xi = xo; xo = t;
    }

    skiphead2_kernel<<<dim3(TT/64, BB), 256, T2_SMEM>>>(
        ah, al, wsh, wsl, skip_b, woh, weh, out_r);
}

// round 15
// speedup vs baseline: 1.2178x; 1.0243x over previous
#include <cuda_runtime.h>
#include <cuda_fp16.h>
#include <math.h>
#include <stdint.h>

// Problem constants
#define BB 4
#define TT 8192
#define CC 128
#define RRC 64       // residual channels
#define SSC 256      // skip channels
#define LLC 16

// Output region offsets (pytree flatten order: out, in_acts, cond)
#define OUT_SZ     (BB*256*TT)
#define INACT_OFF  (OUT_SZ)
#define INACT_SZ   (BB*LLC*128*TT)
#define COND_OFF   (INACT_OFF + INACT_SZ)

#define SQRT_HALF 0.70710678118654752440f

// Scratch (device globals; no allocation allowed)
__device__ float g_x0[BB*RRC*TT];
__device__ float g_x1[BB*RRC*TT];

// Gated activations, fp16 hi/lo planes, layout [l][b][t][64ch]
__device__ __align__(16) __half g_act_h[LLC*BB*TT*64];
__device__ __align__(16) __half g_act_l[LLC*BB*TT*64];

// Pre-packed A-operand fragments (fp16 hi/lo), mma.m16n8k16 layout.
__device__ uint4 g_wd_h[LLC*2048];
__device__ uint4 g_wd_l[LLC*2048];
__device__ uint4 g_ws_h[LLC*2048];
__device__ uint4 g_ws_l[LLC*2048];
__device__ uint4 g_wr_h[15*512];
__device__ uint4 g_wr_l[15*512];
__device__ uint4 g_wc_h[LLC*2048];  // cond_W frags (hi/lo)
__device__ uint4 g_wc_l[LLC*2048];
__device__ uint4 g_wo_h[8192];      // conv_out_W frags (hi only)
__device__ uint4 g_we_h[8192];      // conv_end_W frags (hi only)

// ===========================================================================
// helpers
// ===========================================================================
__device__ __forceinline__ uint32_t smem_u32(const void* p) {
    uint32_t a;
    asm("{ .reg .u64 t; cvta.to.shared.u64 t, %1; cvt.u32.u64 %0, t; }" : "=r"(a) : "l"(p));
    return a;
}
__device__ __forceinline__ void ldsm4(uint32_t* r, uint32_t a) {
    asm volatile("ldmatrix.sync.aligned.m8n8.x4.shared.b16 {%0,%1,%2,%3}, [%4];"
        : "=r"(r[0]), "=r"(r[1]), "=r"(r[2]), "=r"(r[3]) : "r"(a));
}
__device__ __forceinline__ void mma16816(float* d, const uint32_t* a, const uint32_t* b) {
    asm volatile(
        "mma.sync.aligned.m16n8k16.row.col.f32.f16.f16.f32 "
        "{%0,%1,%2,%3}, {%4,%5,%6,%7}, {%8,%9}, {%0,%1,%2,%3};"
        : "+f"(d[0]), "+f"(d[1]), "+f"(d[2]), "+f"(d[3])
        : "r"(a[0]), "r"(a[1]), "r"(a[2]), "r"(a[3]), "r"(b[0]), "r"(b[1]));
}
__device__ __forceinline__ void ldB(uint32_t* fr, const char* sb, int off, int stride,
                                    int n0, int k0, int lane) {
    uint32_t a = smem_u32(sb + off) +
        (uint32_t)(((n0 + ((lane >> 4) & 1) * 8 + (lane & 7)) * stride
                    + k0 + ((lane >> 3) & 1) * 8) << 1);
    ldsm4(fr, a);
}
__device__ __forceinline__ void split2(float v, __half& h, __half& l) {
    h = __float2half_rn(v);
    l = __float2half_rn(v - __half2float(h));
}
__device__ __forceinline__ uint32_t packh2(__half a, __half b) {
    __half2 h = __halves2half2(a, b);
    return *(uint32_t*)&h;
}

#define CP_ASYNC16(dst, src) \
    asm volatile("cp.async.ca.shared.global [%0], [%1], 16;" :: "r"(dst), "l"(src))
#define CP_COMMIT() asm volatile("cp.async.commit_group;" ::: "memory")
#define CP_WAIT0()  asm volatile("cp.async.wait_group 0;" ::: "memory")

// ===========================================================================
// merged weight pre-pack kernel
// ===========================================================================
__device__ __forceinline__ void pack8(const float* v, uint4& hi, uint4& lo) {
    __half eh[8], el[8];
    #pragma unroll
    for (int i = 0; i < 8; i++) split2(v[i], eh[i], el[i]);
    hi.x = packh2(eh[0], eh[1]); hi.y = packh2(eh[2], eh[3]);
    hi.z = packh2(eh[4], eh[5]); hi.w = packh2(eh[6], eh[7]);
    lo.x = packh2(el[0], el[1]); lo.y = packh2(el[2], el[3]);
    lo.z = packh2(el[4], el[5]); lo.w = packh2(el[6], el[7]);
}

__global__ void pack_all_kernel(const float* __restrict__ dilate_W,
                                const float* __restrict__ cond_W,
                                const float* __restrict__ skip_W,
                                const float* __restrict__ res_W,
                                const float* __restrict__ Wout,
                                const float* __restrict__ Wend,
                                uint4* __restrict__ wdh, uint4* __restrict__ wdl,
                                uint4* __restrict__ wch, uint4* __restrict__ wcl,
                                uint4* __restrict__ wsh, uint4* __restrict__ wsl,
                                uint4* __restrict__ wrh, uint4* __restrict__ wrl,
                                uint4* __restrict__ woh, uint4* __restrict__ weh)
{
    const int bx = blockIdx.x, tid = threadIdx.x;
    static const int dr[8] = {0,0,8,8,0,0,8,8};
    static const int dc[8] = {0,1,0,1,8,9,8,9};

    if (bx < 128) {                       // dilate
        int idx = bx*256 + tid;
        int lane = idx & 31, fi = idx >> 5;
        int ks = fi & 7, mt = (fi >> 3) & 7, l = fi >> 6;
        int r = mt*16 + (lane >> 2), cb = ks*16 + (lane & 3)*2;
        float v[8];
        #pragma unroll
        for (int i = 0; i < 8; i++) {
            int row = r + dr[i], col = cb + dc[i];
            v[i] = (col < 64)
                ? dilate_W[((l*128 + row)*64 + col)*2 + 0]
                : dilate_W[((l*128 + row)*64 + (col - 64))*2 + 1];
        }
        uint4 hi, lo; pack8(v, hi, lo);
        wdh[idx] = hi; wdl[idx] = lo;
    } else if (bx < 256) {                // cond
        int idx = (bx-128)*256 + tid;
        int lane = idx & 31, fi = idx >> 5;
        int ks = fi & 7, mt = (fi >> 3) & 7, l = fi >> 6;
        int r = mt*16 + (lane >> 2), cb = ks*16 + (lane & 3)*2;
        float v[8];
        #pragma unroll
        for (int i = 0; i < 8; i++)
            v[i] = cond_W[((size_t)(l*128 + r + dr[i]))*CC + cb + dc[i]];
        uint4 hi, lo; pack8(v, hi, lo);
        wch[idx] = hi; wcl[idx] = lo;
    } else if (bx < 384) {                // skip
        int idx = (bx-256)*256 + tid;
        int lane = idx & 31, fi = idx >> 5;
        int ks = fi & 3, mt = (fi >> 2) & 15, l = fi >> 6;
        int r = mt*16 + (lane >> 2), cb = ks*16 + (lane & 3)*2;
        float v[8];
        #pragma unroll
        for (int i = 0; i < 8; i++)
            v[i] = skip_W[((size_t)l*256 + r + dr[i])*64 + cb + dc[i]];
        uint4 hi, lo; pack8(v, hi, lo);
        wsh[idx] = hi; wsl[idx] = lo;
    } else if (bx < 414) {                // res
        int idx = (bx-384)*256 + tid;
        if (idx >= 7680) return;
        int lane = idx & 31, fi = idx >> 5;
        int ks = fi & 3, mt = (fi >> 2) & 3, l = fi >> 4;
        int r = mt*16 + (lane >> 2), cb = ks*16 + (lane & 3)*2;
        float v[8];
        #pragma unroll
        for (int i = 0; i < 8; i++)
            v[i] = res_W[((size_t)l*64 + r + dr[i])*64 + cb + dc[i]];
        uint4 hi, lo; pack8(v, hi, lo);
        wrh[idx] = hi; wrl[idx] = lo;
    } else {                              // Wout / Wend (hi only)
        const float* W = (bx < 446) ? Wout : Wend;
        uint4* outp    = (bx < 446) ? woh : weh;
        int idx = ((bx < 446) ? (bx-414) : (bx-446))*256 + tid;
        int lane = idx & 31, fi = idx >> 5;
        int ks = fi & 15, mt = fi >> 4;
        int r = mt*16 + (lane >> 2), cb = ks*16 + (lane & 3)*2;
        __half eh[8];
        #pragma unroll
        for (int i = 0; i < 8; i++)
            eh[i] = __float2half_rn(W[(r + dr[i])*256 + cb + dc[i]]);
        uint4 hi;
        hi.x = packh2(eh[0], eh[1]); hi.y = packh2(eh[2], eh[3]);
        hi.z = packh2(eh[4], eh[5]); hi.w = packh2(eh[6], eh[7]);
        outp[idx] = hi;
    }
}

// ===========================================================================
// embed
// ===========================================================================
__global__ void embed_kernel(const int* __restrict__ tokens,
                             const float* __restrict__ embed,
                             float* __restrict__ x0)
{
    __shared__ int tok[256];
    const int t0 = blockIdx.x * 256;
    const int b  = blockIdx.y;
    tok[threadIdx.x] = tokens[b*TT + t0 + threadIdx.x];
    __syncthreads();
    const int v = tok[threadIdx.x];
    #pragma unroll 4
    for (int r = 0; r < RRC; r++)
        x0[(b*RRC + r)*TT + t0 + threadIdx.x] = embed[v*RRC + r];
}

// ===========================================================================
// cond v4 (unchanged from R12)
// ===========================================================================
#define C4_FH 0
#define C4_FL 8704
#define C4_SMEM 17408

__global__ void __launch_bounds__(128, 8)
cond_mma4_kernel(const float* __restrict__ features,
                 const uint4* __restrict__ wc_h, const uint4* __restrict__ wc_l,
                 const float* __restrict__ cond_b,
                 float* __restrict__ cond_out)
{
    extern __shared__ char sb[];
    const int tid = threadIdx.x, wid = tid >> 5, lane = tid & 31;
    const int g = lane >> 2, tg = lane & 3;
    const int t0 = blockIdx.x * 32;
    const int b  = blockIdx.y;

    {
        __half* FH = (__half*)(sb + C4_FH);
        __half* FL = (__half*)(sb + C4_FL);
        for (int e = tid; e < 4096; e += 128) {
            int t = e & 31, k = e >> 5;
            float v = features[((size_t)b*CC + k)*TT + t0 + t];
            __half h, lo; split2(v, h, lo);
            FH[t*136 + k] = h; FL[t*136 + k] = lo;
        }
    }
    __syncthreads();

    const int m0 = wid * 32;

    for (int l = 0; l < LLC; l++) {
        float acc[2][4][4] = {};
        const uint4* ph = wc_h + (size_t)l * 2048;
        const uint4* pl = wc_l + (size_t)l * 2048;
        #pragma unroll
        for (int ks = 0; ks < 8; ks++) {
            #pragma unroll
            for (int p = 0; p < 2; p++) {
                uint32_t bh[4], bl[4];
                ldB(bh, sb, C4_FH, 136, p*16, ks*16, lane);
                ldB(bl, sb, C4_FL, 136, p*16, ks*16, lane);
                {
                    uint4 A0 = ph[((wid*2    )*8 + ks)*32 + lane];
                    uint4 A1 = ph[((wid*2 + 1)*8 + ks)*32 + lane];
                    #pragma unroll
                    for (int q = 0; q < 2; q++) {
                        int nt = p*2 + q;
                        mma16816(acc[0][nt], (const uint32_t*)&A0, &bh[q*2]);
                        mma16816(acc[0][nt], (const uint32_t*)&A0, &bl[q*2]);
                        mma16816(acc[1][nt], (const uint32_t*)&A1, &bh[q*2]);
                        mma16816(acc[1][nt], (const uint32_t*)&A1, &bl[q*2]);
                    }
                }
                {
                    uint4 A0 = pl[((wid*2    )*8 + ks)*32 + lane];
                    uint4 A1 = pl[((wid*2 + 1)*8 + ks)*32 + lane];
                    #pragma unroll
                    for (int q = 0; q < 2; q++) {
                        int nt = p*2 + q;
                        mma16816(acc[0][nt], (const uint32_t*)&A0, &bh[q*2]);
                        mma16816(acc[1][nt], (const uint32_t*)&A1, &bh[q*2]);
                    }
                }
            }
        }
        #pragma unroll
        for (int mt = 0; mt < 2; mt++)
            #pragma unroll
            for (int r = 0; r < 2; r++) {
                int o = m0 + mt*16 + r*8 + g;
                float bias = cond_b[l*128 + o];
                float* row = cond_out + ((size_t)(b*LLC + l)*128 + o)*TT + t0;
                #pragma unroll
                for (int nt = 0; nt < 4; nt++) {
                    int tc = nt*8 + 2*tg;
                    float2 rv = make_float2(acc[mt][nt][r*2+0] + bias,
                                            acc[mt][nt][r*2+1] + bias);
                    *(float2*)(row + tc) = rv;
                }
            }
    }
}

// ===========================================================================
// layer v8: paired-row warp ownership -> in-register gated activation.
// Warp w owns rows [16w,16w+16) and [64+16w, 64+16w+16): acc[0] = tanh-half,
// acc[1] = sigmoid-half at the SAME t. Only TWO barriers. 128 thr, 8 CTAs/SM.
// smem: XH[32][136] @0 (8704), XL @8704 (8704), AH[32][72] @17408 (4608),
//       AL @22016 (4608). total 26624; 8x = 213KB.
// ===========================================================================
#define L8_XH   0
#define L8_XL   8704
#define L8_AH   17408
#define L8_AL   22016
#define L8_SMEM 26624

__global__ void __launch_bounds__(128, 8)
layer_mma8_kernel(const float* __restrict__ x_in,
                  float* __restrict__ x_out,
                  const uint4* __restrict__ wd_h, const uint4* __restrict__ wd_l,
                  const float* __restrict__ dilate_b,
                  const uint4* __restrict__ wr_h, const uint4* __restrict__ wr_l,
                  const float* __restrict__ res_b,
                  const float* __restrict__ cond_g,
                  float* __restrict__ inacts_g,
                  __half* __restrict__ act_h, __half* __restrict__ act_l,
                  int layer, int dil, int last)
{
    extern __shared__ char sb[];
    const int tid = threadIdx.x, wid = tid >> 5, lane = tid & 31;
    const int g = lane >> 2, tg = lane & 3;
    const int t0 = blockIdx.x * 32;
    const int b  = blockIdx.y;

    // ---- stage X halves: [t:32][ks:128]
    {
        __half* XH = (__half*)(sb + L8_XH);
        __half* XL = (__half*)(sb + L8_XL);
        const float* xb = x_in + (size_t)b * RRC * TT;
        for (int e = tid; e < 4096; e += 128) {
            int t = e & 31, ks = e >> 5;
            float v;
            if (ks < 64) {
                int tp = t0 + t - dil;
                v = (tp >= 0) ? xb[ks*TT + tp] : 0.f;
            } else {
                v = xb[(ks - 64)*TT + t0 + t];
            }
            __half h, lo; split2(v, h, lo);
            XH[t*136 + ks] = h; XL[t*136 + ks] = lo;
        }
    }
    __syncthreads();   // bar1: X staged

    // ---- GEMM1 with paired-row mtiles: mtA = wid (rows 16w..), mtB = wid+4
    // (rows 64+16w..). reg-lean 3-pass.
    float acc[2][4][4] = {};
    {
        const uint4* ph = wd_h + (size_t)layer * 2048;
        const uint4* pl = wd_l + (size_t)layer * 2048;
        #pragma unroll
        for (int ks = 0; ks < 8; ks++) {
            #pragma unroll
            for (int p = 0; p < 2; p++) {
                uint32_t bh[4], bl[4];
                ldB(bh, sb, L8_XH, 136, p*16, ks*16, lane);
                ldB(bl, sb, L8_XL, 136, p*16, ks*16, lane);
                {
                    uint4 A0 = ph[((wid    )*8 + ks)*32 + lane];
                    uint4 A1 = ph[((wid + 4)*8 + ks)*32 + lane];
                    #pragma unroll
                    for (int q = 0; q < 2; q++) {
                        int nt = p*2 + q;
                        mma16816(acc[0][nt], (const uint32_t*)&A0, &bh[q*2]);
                        mma16816(acc[0][nt], (const uint32_t*)&A0, &bl[q*2]);
                        mma16816(acc[1][nt], (const uint32_t*)&A1, &bh[q*2]);
                        mma16816(acc[1][nt], (const uint32_t*)&A1, &bl[q*2]);
                    }
                }
                {
                    uint4 A0 = pl[((wid    )*8 + ks)*32 + lane];
                    uint4 A1 = pl[((wid + 4)*8 + ks)*32 + lane];
                    #pragma unroll
                    for (int q = 0; q < 2; q++) {
                        int nt = p*2 + q;
                        mma16816(acc[0][nt], (const uint32_t*)&A0, &bh[q*2]);
                        mma16816(acc[1][nt], (const uint32_t*)&A1, &bh[q*2]);
                    }
                }
            }
        }
    }

    // ---- fused epilogue: ia -> inacts (both halves); in-register activation
    // -> AH/AL smem (separate region, no hazard with X)
    {
        __half* AH = (__half*)(sb + L8_AH);
        __half* AL = (__half*)(sb + L8_AL);
        #pragma unroll
        for (int r = 0; r < 2; r++) {
            int o = wid*16 + r*8 + g;           // o < 64 (tanh half)
            float b0 = dilate_b[layer*128 + o];
            float b1 = dilate_b[layer*128 + o + 64];
            size_t row0 = ((size_t)(b*LLC + layer)*128 + o)*TT + t0;
            size_t row1 = row0 + (size_t)64*TT;
            float*       ia0p = inacts_g + row0;
            float*       ia1p = inacts_g + row1;
            const float* cv0p = cond_g + row0;
            const float* cv1p = cond_g + row1;
            #pragma unroll
            for (int nt = 0; nt < 4; nt++) {
                int tc = nt*8 + 2*tg;
                float2 cv0 = *(const float2*)(cv0p + tc);
                float2 cv1 = *(const float2*)(cv1p + tc);
                float ia0x = acc[0][nt][r*2+0] + b0;
                float ia0y = acc[0][nt][r*2+1] + b0;
                float ia1x = acc[1][nt][r*2+0] + b1;
                float ia1y = acc[1][nt][r*2+1] + b1;
                *(float2*)(ia0p + tc) = make_float2(ia0x, ia0y);
                *(float2*)(ia1p + tc) = make_float2(ia1x, ia1y);
                float ax = tanhf(ia0x + cv0.x) * (1.f / (1.f + __expf(-(ia1x + cv1.x))));
                float ay = tanhf(ia0y + cv0.y) * (1.f / (1.f + __expf(-(ia1y + cv1.y))));
                __half hx, lx, hy, ly;
                split2(ax, hx, lx);
                split2(ay, hy, ly);
                AH[tc*72 + o]       = hx;
                AH[(tc + 1)*72 + o] = hy;
                AL[tc*72 + o]       = lx;
                AL[(tc + 1)*72 + o] = ly;
            }
        }
    }
    __syncthreads();   // bar2: AH/AL complete

    // ---- store act planes (consumed by skiphead)
    {
        uint4* gh = (uint4*)(act_h + ((size_t)(layer*BB + b)*TT + t0)*64);
        uint4* gl = (uint4*)(act_l + ((size_t)(layer*BB + b)*TT + t0)*64);
        for (int i = tid; i < 256; i += 128) {
            int t = i >> 3, j = i & 7;
            gh[t*8 + j] = *(const uint4*)(sb + L8_AH + t*144 + j*16);
            gl[t*8 + j] = *(const uint4*)(sb + L8_AL + t*144 + j*16);
        }
    }

    // ---- GEMM3: res (M=64, N=32, K=64), reg-lean 3-pass; residual x update
    if (!last) {
        const int mi3 = wid >> 1, ni3 = wid & 1;
        const int m0r = mi3 * 32, n0r = ni3 * 16;
        const uint4* ph = wr_h + (size_t)layer * 512;
        const uint4* pl = wr_l + (size_t)layer * 512;
        float acc3[2][2][4] = {};
        #pragma unroll
        for (int ks = 0; ks < 4; ks++) {
            uint32_t bh[4], bl[4];
            ldB(bh, sb, L8_AH, 72, n0r, ks*16, lane);
            ldB(bl, sb, L8_AL, 72, n0r, ks*16, lane);
            {
                uint4 A0 = ph[((mi3*2    )*4 + ks)*32 + lane];
                uint4 A1 = ph[((mi3*2 + 1)*4 + ks)*32 + lane];
                #pragma unroll
                for (int q = 0; q < 2; q++) {
                    mma16816(acc3[0][q], (const uint32_t*)&A0, &bh[q*2]);
                    mma16816(acc3[0][q], (const uint32_t*)&A0, &bl[q*2]);
                    mma16816(acc3[1][q], (const uint32_t*)&A1, &bh[q*2]);
                    mma16816(acc3[1][q], (const uint32_t*)&A1, &bl[q*2]);
                }
            }
            {
                uint4 A0 = pl[((mi3*2    )*4 + ks)*32 + lane];
                uint4 A1 = pl[((mi3*2 + 1)*4 + ks)*32 + lane];
                #pragma unroll
                for (int q = 0; q < 2; q++) {
                    mma16816(acc3[0][q], (const uint32_t*)&A0, &bh[q*2]);
                    mma16816(acc3[1][q], (const uint32_t*)&A1, &bh[q*2]);
                }
            }
        }
        #pragma unroll
        for (int mt = 0; mt < 2; mt++)
            #pragma unroll
            for (int r = 0; r < 2; r++) {
                int o = m0r + mt*16 + r*8 + g;
                float rb = res_b[layer*RRC + o];
                const float* xi = x_in  + ((size_t)b*RRC + o)*TT + t0;
                float*       xo = x_out + ((size_t)b*RRC + o)*TT + t0;
                #pragma unroll
                for (int nt = 0; nt < 2; nt++) {
                    int tc = n0r + nt*8 + 2*tg;
                    float2 xv = *(const float2*)(xi + tc);
                    float2 rv;
                    rv.x = (acc3[mt][nt][r*2+0] + rb + xv.x) * SQRT_HALF;
                    rv.y = (acc3[mt][nt][r*2+1] + rb + xv.y) * SQRT_HALF;
                    *(float2*)(xo + tc) = rv;
                }
            }
    }
}

// ===========================================================================
// skiphead v2 (unchanged)
// ===========================================================================
#define TB_SZ  18432
#define T2_SMEM 36864

__global__ void __launch_bounds__(256, 2)
skiphead2_kernel(const __half* __restrict__ act_h, const __half* __restrict__ act_l,
                 const uint4* __restrict__ ws_h, const uint4* __restrict__ ws_l,
                 const float* __restrict__ skip_b,
                 const uint4* __restrict__ wo_h, const uint4* __restrict__ we_h,
                 float* __restrict__ out)
{
    extern __shared__ char sb[];
    uint32_t sb_u = smem_u32(sb);
    const int tid = threadIdx.x, wid = tid >> 5, lane = tid & 31;
    const int g = lane >> 2, tg = lane & 3;
    const int t0 = blockIdx.x * 64;
    const int b  = blockIdx.y;

    float acc[2][8][4] = {};

    auto stage = [&](int l, int buf) {
        const uint4* gh = (const uint4*)(act_h + ((size_t)(l*BB + b)*TT + t0)*64);
        const uint4* gl = (const uint4*)(act_l + ((size_t)(l*BB + b)*TT + t0)*64);
        uint32_t dh = sb_u + buf*TB_SZ;
        uint32_t dl = dh + 9216;
        for (int i = tid; i < 512; i += 256) {
            int t = i >> 3, j = i & 7;
            CP_ASYNC16(dh + t*144 + j*16, gh + t*8 + j);
            CP_ASYNC16(dl + t*144 + j*16, gl + t*8 + j);
        }
        CP_COMMIT();
    };

    stage(0, 0);
    CP_WAIT0();
    __syncthreads();

    for (int l = 0; l < LLC; l++) {
        int cur = l & 1;
        if (l + 1 < LLC) stage(l + 1, cur ^ 1);

        int offH = cur*TB_SZ, offL = offH + 9216;
        const uint4* ph = ws_h + (size_t)l * 2048;
        const uint4* pl = ws_l + (size_t)l * 2048;
        for (int ks = 0; ks < 4; ks++) {
            uint4 A0h = ph[((wid*2    )*4 + ks)*32 + lane];
            uint4 A1h = ph[((wid*2 + 1)*4 + ks)*32 + lane];
            uint4 A0l = pl[((wid*2    )*4 + ks)*32 + lane];
            uint4 A1l = pl[((wid*2 + 1)*4 + ks)*32 + lane];
            #pragma unroll
            for (int p = 0; p < 4; p++) {
                uint32_t bh[4], bl[4];
                ldB(bh, sb, offH, 72, p*16, ks*16, lane);
                ldB(bl, sb, offL, 72, p*16, ks*16, lane);
                #pragma unroll
                for (int q = 0; q < 2; q++) {
                    int nt = p*2 + q;
                    mma16816(acc[0][nt], (const uint32_t*)&A0h, &bh[q*2]);
                    mma16816(acc[0][nt], (const uint32_t*)&A0h, &bl[q*2]);
                    mma16816(acc[0][nt], (const uint32_t*)&A0l, &bh[q*2]);
                    mma16816(acc[1][nt], (const uint32_t*)&A1h, &bh[q*2]);
                    mma16816(acc[1][nt], (const uint32_t*)&A1h, &bl[q*2]);
                    mma16816(acc[1][nt], (const uint32_t*)&A1l, &bh[q*2]);
                }
            }
        }
        if (l + 1 < LLC) CP_WAIT0();
        __syncthreads();
    }

    {
        __half* H = (__half*)sb;
        #pragma unroll
        for (int mt = 0; mt < 2; mt++)
            #pragma unroll
            for (int r = 0; r < 2; r++) {
                int o = wid*32 + mt*16 + r*8 + g;
                float bs = 0.f;
                #pragma unroll
                for (int l = 0; l < LLC; l++) bs += skip_b[l*SSC + o];
                #pragma unroll
                for (int nt = 0; nt < 8; nt++) {
                    int t = nt*8 + tg*2;
                    H[t*264 + o]     = __float2half_rn(fmaxf(acc[mt][nt][r*2+0] + bs, 0.f));
                    H[(t+1)*264 + o] = __float2half_rn(fmaxf(acc[mt][nt][r*2+1] + bs, 0.f));
                }
            }
    }
    __syncthreads();

    float acc2[2][8][4] = {};
    for (int ks = 0; ks < 16; ks++) {
        uint4 A0 = wo_h[((wid*2    )*16 + ks)*32 + lane];
        uint4 A1 = wo_h[((wid*2 + 1)*16 + ks)*32 + lane];
        #pragma unroll
        for (int p = 0; p < 4; p++) {
            uint32_t bh[4];
            ldB(bh, sb, 0, 264, p*16, ks*16, lane);
            #pragma unroll
            for (int q = 0; q < 2; q++) {
                int nt = p*2 + q;
                mma16816(acc2[0][nt], (const uint32_t*)&A0, &bh[q*2]);
                mma16816(acc2[1][nt], (const uint32_t*)&A1, &bh[q*2]);
            }
        }
    }
    __syncthreads();
    {
        __half* H = (__half*)sb;
        #pragma unroll
        for (int mt = 0; mt < 2; mt++)
            #pragma unroll
            for (int r = 0; r < 2; r++) {
                int o = wid*32 + mt*16 + r*8 + g;
                #pragma unroll
                for (int nt = 0; nt < 8; nt++) {
                    int t = nt*8 + tg*2;
                    H[t*264 + o]     = __float2half_rn(fmaxf(acc2[mt][nt][r*2+0], 0.f));
                    H[(t+1)*264 + o] = __float2half_rn(fmaxf(acc2[mt][nt][r*2+1], 0.f));
                }
            }
    }
    __syncthreads();

    float acc3[2][8][4] = {};
    for (int ks = 0; ks < 16; ks++) {
        uint4 A0 = we_h[((wid*2    )*16 + ks)*32 + lane];
        uint4 A1 = we_h[((wid*2 + 1)*16 + ks)*32 + lane];
        #pragma unroll
        for (int p = 0; p < 4; p++) {
            uint32_t bh[4];
            ldB(bh, sb, 0, 264, p*16, ks*16, lane);
            #pragma unroll
            for (int q = 0; q < 2; q++) {
                int nt = p*2 + q;
                mma16816(acc3[0][nt], (const uint32_t*)&A0, &bh[q*2]);
                mma16816(acc3[1][nt], (const uint32_t*)&A1, &bh[q*2]);
            }
        }
    }
    #pragma unroll
    for (int mt = 0; mt < 2; mt++)
        #pragma unroll
        for (int r = 0; r < 2; r++) {
            int o = wid*32 + mt*16 + r*8 + g;
            float* op = out + ((size_t)b*256 + o)*TT;
            #pragma unroll
            for (int nt = 0; nt < 8; nt++) {
                int tc = t0 + nt*8 + 2*tg;
                if (tc + 1 < TT) op[tc + 1] = acc3[mt][nt][r*2+0];
                if (tc + 2 < TT) op[tc + 2] = acc3[mt][nt][r*2+1];
            }
        }
    if (blockIdx.x == 0) out[((size_t)b*256 + tid)*TT] = 0.f;
}

// ===========================================================================
extern "C" void kernel_launch(void* const* d_in, const int* in_sizes, int n_in,
                              void* d_out, int out_size)
{
    const float* features   = (const float*)d_in[0];
    const int*   tokens     = (const int*)  d_in[1];
    const float* embed      = (const float*)d_in[2];
    const float* cond_W     = (const float*)d_in[3];
    const float* cond_b     = (const float*)d_in[4];
    const float* dilate_W   = (const float*)d_in[5];
    const float* dilate_b   = (const float*)d_in[6];
    const float* res_W      = (const float*)d_in[7];
    const float* res_b      = (const float*)d_in[8];
    const float* skip_W     = (const float*)d_in[9];
    const float* skip_b     = (const float*)d_in[10];
    const float* conv_out_W = (const float*)d_in[11];
    const float* conv_end_W = (const float*)d_in[12];
    float* outp = (float*)d_out;

    float* out_r   = outp;
    float* inact_r = outp + INACT_OFF;
    float* cond_r  = outp + COND_OFF;

    float *x0, *x1;
    __half *ah, *al;
    uint4 *wdh, *wdl, *wsh, *wsl, *wrh, *wrl, *wch, *wcl, *woh, *weh;
    cudaGetSymbolAddress((void**)&x0,  g_x0);
    cudaGetSymbolAddress((void**)&x1,  g_x1);
    cudaGetSymbolAddress((void**)&ah,  g_act_h);
    cudaGetSymbolAddress((void**)&al,  g_act_l);
    cudaGetSymbolAddress((void**)&wdh, g_wd_h);
    cudaGetSymbolAddress((void**)&wdl, g_wd_l);
    cudaGetSymbolAddress((void**)&wsh, g_ws_h);
    cudaGetSymbolAddress((void**)&wsl, g_ws_l);
    cudaGetSymbolAddress((void**)&wrh, g_wr_h);
    cudaGetSymbolAddress((void**)&wrl, g_wr_l);
    cudaGetSymbolAddress((void**)&wch, g_wc_h);
    cudaGetSymbolAddress((void**)&wcl, g_wc_l);
    cudaGetSymbolAddress((void**)&woh, g_wo_h);
    cudaGetSymbolAddress((void**)&weh, g_we_h);

    static const int DIL[LLC] = {1,2,4,8,16,32,64,128,256,1,2,4,8,16,32,64};

    cudaFuncSetAttribute(cond_mma4_kernel,  cudaFuncAttributeMaxDynamicSharedMemorySize, C4_SMEM);
    cudaFuncSetAttribute(layer_mma8_kernel, cudaFuncAttributeMaxDynamicSharedMemorySize, L8_SMEM);
    cudaFuncSetAttribute(skiphead2_kernel,  cudaFuncAttributeMaxDynamicSharedMemorySize, T2_SMEM);

    pack_all_kernel<<<478, 256>>>(dilate_W, cond_W, skip_W, res_W, conv_out_W, conv_end_W,
                                  wdh, wdl, wch, wcl, wsh, wsl, wrh, wrl, woh, weh);

    embed_kernel<<<dim3(TT/256, BB), 256>>>(tokens, embed, x0);
    cond_mma4_kernel<<<dim3(TT/32, BB), 128, C4_SMEM>>>(features, wch, wcl, cond_b, cond_r);

    float* xi = x0;
    float* xo = x1;
    for (int i = 0; i < LLC; i++) {
        layer_mma8_kernel<<<dim3(TT/32, BB), 128, L8_SMEM>>>(
            xi, xo, wdh, wdl, dilate_b, wrh, wrl, res_b,
            cond_r, inact_r, ah, al,
            i, DIL[i], (i == LLC-1) ? 1 : 0);
        float* t = xi; xi = xo; xo = t;
    }

    skiphead2_kernel<<<dim3(TT/64, BB), 256, T2_SMEM>>>(
        ah, al, wsh, wsl, skip_b, woh, weh, out_r);
}